// round 2
// baseline (speedup 1.0000x reference)
#include <cuda_runtime.h>
#include <cstdint>

// Problem constants
#define BB   128      // batch
#define TT   64       // timesteps
#define NIN  1024
#define NH   4096
#define NOUT 1024
#define NSEG 8
#define SEGSZ 512     // NH / NSEG
#define LCAP 256      // minority list capacity per segment (<= SEGSZ/2)

// ---------------- device scratch (static, no allocations) ----------------
__device__ float d_A[BB * TT * NH];       // fc1 output, row m = b*TT + t  (128 MB)
__device__ float d_hmem[BB * NH];
__device__ float d_spk[BB * NH];
__device__ float d_omem[BB * NOUT];
__device__ int   d_list[2][BB][NSEG][LCAP];
__device__ int   d_cnt[2][BB][NSEG];      // count | (mode << 16); mode=1 => complement list
__device__ float d_csrec[NSEG][NH];       // per-segment column sums of W_rec
__device__ float d_csout[NSEG][NOUT];     // per-segment column sums of W_out

// ---------------- init ----------------
__global__ void init_state() {
    int i = blockIdx.x * blockDim.x + threadIdx.x;
    if (i < BB * NH)   { d_hmem[i] = 0.0f; d_spk[i] = 0.0f; }
    if (i < BB * NOUT) { d_omem[i] = 0.0f; }
    if (i < 2 * BB * NSEG) { ((int*)d_cnt)[i] = 0; }
}

// ---------------- column sums ----------------
__global__ void colsum_rec(const float* __restrict__ Wrec) {
    int s   = blockIdx.y;
    int col = blockIdx.x * blockDim.x + threadIdx.x;   // grid.x = NH/256
    float sum = 0.0f;
    const float* base = Wrec + (size_t)(s * SEGSZ) * NH + col;
    #pragma unroll 8
    for (int r = 0; r < SEGSZ; r++) sum += base[(size_t)r * NH];
    d_csrec[s][col] = sum;
}

__global__ void colsum_out(const float* __restrict__ Wout) {
    int s   = blockIdx.y;
    int col = blockIdx.x * blockDim.x + threadIdx.x;   // grid.x = NOUT/256
    float sum = 0.0f;
    const float* base = Wout + (size_t)(s * SEGSZ) * NOUT + col;
    #pragma unroll 8
    for (int r = 0; r < SEGSZ; r++) sum += base[(size_t)r * NOUT];
    d_csout[s][col] = sum;
}

// ---------------- fc1 SGEMM: d_A[m][n] = X[m][:] @ W[:, n]  (M=8192,N=4096,K=1024) ----------------
__global__ __launch_bounds__(256) void sgemm_fc1(const float* __restrict__ X,
                                                 const float* __restrict__ W) {
    const int N = NH, K = NIN;
    __shared__ float As[8][128];
    __shared__ float Bs[8][128];
    int bx = blockIdx.x;                  // N / 128 = 32
    int by = blockIdx.y;                  // M / 128 = 64
    int tid = threadIdx.x;

    int lx_m = tid >> 1;                  // 0..127
    int lx_k = (tid & 1) << 2;            // 0 or 4
    int lw_k = tid >> 5;                  // 0..7
    int lw_n = (tid & 31) << 2;           // 0..124
    int tm = (tid >> 4) << 3;             // 0..120 step 8
    int tn = (tid & 15) << 3;             // 0..120 step 8

    const float* xp = X + (size_t)(by * 128 + lx_m) * K + lx_k;
    const float* wp = W + (size_t)lw_k * N + bx * 128 + lw_n;

    float acc[8][8];
    #pragma unroll
    for (int i = 0; i < 8; i++)
        #pragma unroll
        for (int j = 0; j < 8; j++) acc[i][j] = 0.0f;

    for (int k0 = 0; k0 < K; k0 += 8) {
        float4 xv = *(const float4*)xp;
        float4 wv = *(const float4*)wp;
        As[lx_k + 0][lx_m] = xv.x;
        As[lx_k + 1][lx_m] = xv.y;
        As[lx_k + 2][lx_m] = xv.z;
        As[lx_k + 3][lx_m] = xv.w;
        *(float4*)&Bs[lw_k][lw_n] = wv;
        __syncthreads();

        #pragma unroll
        for (int kk = 0; kk < 8; kk++) {
            float am[8], bn[8];
            *(float4*)(am)     = *(const float4*)&As[kk][tm];
            *(float4*)(am + 4) = *(const float4*)&As[kk][tm + 4];
            *(float4*)(bn)     = *(const float4*)&Bs[kk][tn];
            *(float4*)(bn + 4) = *(const float4*)&Bs[kk][tn + 4];
            #pragma unroll
            for (int i = 0; i < 8; i++)
                #pragma unroll
                for (int j = 0; j < 8; j++)
                    acc[i][j] += am[i] * bn[j];
        }
        __syncthreads();
        xp += 8;
        wp += (size_t)8 * N;
    }

    float* cp = d_A + (size_t)(by * 128 + tm) * N + bx * 128 + tn;
    #pragma unroll
    for (int i = 0; i < 8; i++) {
        float4 v0 = make_float4(acc[i][0], acc[i][1], acc[i][2], acc[i][3]);
        float4 v1 = make_float4(acc[i][4], acc[i][5], acc[i][6], acc[i][7]);
        *(float4*)&cp[(size_t)i * N]     = v0;
        *(float4*)&cp[(size_t)i * N + 4] = v1;
    }
}

// ---------------- per-step membrane update + spike + list build ----------------
// grid (BB, NSEG), 128 threads; each thread owns 4 hidden cols.
__global__ __launch_bounds__(128) void step_update(const float* __restrict__ Wrec, int t) {
    int b = blockIdx.x, seg = blockIdx.y, tid = threadIdx.x;
    __shared__ int sh_idx[NSEG * LCAP];
    __shared__ int sh_cnt[NSEG];
    __shared__ int sh_off[NSEG];
    __shared__ int s_total, s_w;

    int rb = (t & 1) ^ 1;   // buffer holding previous step's lists
    int wb = t & 1;         // buffer for this step's lists

    if (tid < NSEG) sh_cnt[tid] = d_cnt[rb][b][tid];
    if (tid == 0) { s_total = 0; s_w = 0; }
    __syncthreads();
    if (tid == 0) {
        int off = 0;
        for (int s = 0; s < NSEG; s++) { sh_off[s] = off; off += (sh_cnt[s] & 0xFFFF); }
    }
    __syncthreads();

    int col0 = seg * SEGSZ + tid * 4;     // global hidden index for this thread's 4 cols
    float4 r = make_float4(0.f, 0.f, 0.f, 0.f);

    // complement-mode base (column sums) + stage index lists into shared
    for (int s = 0; s < NSEG; s++) {
        int cm = sh_cnt[s];
        int cnt  = cm & 0xFFFF;
        int mode = cm >> 16;
        if (mode) {
            float4 cs = *(const float4*)&d_csrec[s][col0];
            r.x += cs.x; r.y += cs.y; r.z += cs.z; r.w += cs.w;
        }
        int base = sh_off[s];
        int tag  = (int)((unsigned)mode << 31);
        for (int j = tid; j < cnt; j += blockDim.x)
            sh_idx[base + j] = d_list[rb][b][s][j] | tag;
    }
    __syncthreads();
    int total = sh_off[NSEG - 1] + (sh_cnt[NSEG - 1] & 0xFFFF);

    // gather/scatter-sum of W_rec rows (sign per segment mode)
    for (int j = 0; j < total; j++) {
        int v = sh_idx[j];
        float sg = (v >= 0) ? 1.0f : -1.0f;
        const float4 w = *(const float4*)&Wrec[(size_t)(v & 0xFFF) * NH + col0];
        r.x = fmaf(sg, w.x, r.x);
        r.y = fmaf(sg, w.y, r.y);
        r.z = fmaf(sg, w.z, r.z);
        r.w = fmaf(sg, w.w, r.w);
    }

    // membrane update
    size_t aidx = (size_t)(b * TT + t) * NH + col0;
    float4 a  = *(const float4*)&d_A[aidx];
    size_t hidx = (size_t)b * NH + col0;
    float4 hm = *(float4*)&d_hmem[hidx];
    float4 sp = *(float4*)&d_spk[hidx];

    hm.x = 0.9f * hm.x * (1.0f - sp.x) + a.x + 0.1f * r.x;
    hm.y = 0.9f * hm.y * (1.0f - sp.y) + a.y + 0.1f * r.y;
    hm.z = 0.9f * hm.z * (1.0f - sp.z) + a.z + 0.1f * r.z;
    hm.w = 0.9f * hm.w * (1.0f - sp.w) + a.w + 0.1f * r.w;

    float4 sn;
    sn.x = hm.x >= 0.5f ? 1.0f : 0.0f;
    sn.y = hm.y >= 0.5f ? 1.0f : 0.0f;
    sn.z = hm.z >= 0.5f ? 1.0f : 0.0f;
    sn.w = hm.w >= 0.5f ? 1.0f : 0.0f;

    *(float4*)&d_hmem[hidx] = hm;
    *(float4*)&d_spk[hidx]  = sn;

    int c = (int)(sn.x + sn.y + sn.z + sn.w);
    atomicAdd(&s_total, c);
    __syncthreads();

    int mode = (s_total > (SEGSZ / 2)) ? 1 : 0;   // minority coding
    float want = mode ? 0.0f : 1.0f;
    int loc[4]; int n = 0;
    if (sn.x == want) loc[n++] = col0 + 0;
    if (sn.y == want) loc[n++] = col0 + 1;
    if (sn.z == want) loc[n++] = col0 + 2;
    if (sn.w == want) loc[n++] = col0 + 3;
    if (n) {
        int p = atomicAdd(&s_w, n);
        for (int k = 0; k < n; k++) d_list[wb][b][seg][p + k] = loc[k];
    }
    __syncthreads();
    if (tid == 0) d_cnt[wb][b][seg] = s_w | (mode << 16);
}

// ---------------- per-step readout: o_mem = tau*o_mem + spk@W_out; out[b,t,:] = o_mem ----------------
// grid (BB, 2), 128 threads; each thread owns 4 output cols (2*128*4 = 1024).
__global__ __launch_bounds__(128) void step_out(const float* __restrict__ Wout,
                                                float* __restrict__ out, int t) {
    int b = blockIdx.x, half = blockIdx.y, tid = threadIdx.x;
    __shared__ int sh_idx[NSEG * LCAP];
    __shared__ int sh_cnt[NSEG];
    __shared__ int sh_off[NSEG];

    int wb = t & 1;   // lists written by step_update(t)
    if (tid < NSEG) sh_cnt[tid] = d_cnt[wb][b][tid];
    __syncthreads();
    if (tid == 0) {
        int off = 0;
        for (int s = 0; s < NSEG; s++) { sh_off[s] = off; off += (sh_cnt[s] & 0xFFFF); }
    }
    __syncthreads();

    int col0 = half * 512 + tid * 4;
    float4 u = make_float4(0.f, 0.f, 0.f, 0.f);

    for (int s = 0; s < NSEG; s++) {
        int cm = sh_cnt[s];
        int cnt  = cm & 0xFFFF;
        int mode = cm >> 16;
        if (mode) {
            float4 cs = *(const float4*)&d_csout[s][col0];
            u.x += cs.x; u.y += cs.y; u.z += cs.z; u.w += cs.w;
        }
        int base = sh_off[s];
        int tag  = (int)((unsigned)mode << 31);
        for (int j = tid; j < cnt; j += blockDim.x)
            sh_idx[base + j] = d_list[wb][b][s][j] | tag;
    }
    __syncthreads();
    int total = sh_off[NSEG - 1] + (sh_cnt[NSEG - 1] & 0xFFFF);

    for (int j = 0; j < total; j++) {
        int v = sh_idx[j];
        float sg = (v >= 0) ? 1.0f : -1.0f;
        const float4 w = *(const float4*)&Wout[(size_t)(v & 0xFFF) * NOUT + col0];
        u.x = fmaf(sg, w.x, u.x);
        u.y = fmaf(sg, w.y, u.y);
        u.z = fmaf(sg, w.z, u.z);
        u.w = fmaf(sg, w.w, u.w);
    }

    size_t oidx = (size_t)b * NOUT + col0;
    float4 o = *(float4*)&d_omem[oidx];
    o.x = 0.9f * o.x + u.x;
    o.y = 0.9f * o.y + u.y;
    o.z = 0.9f * o.z + u.z;
    o.w = 0.9f * o.w + u.w;
    *(float4*)&d_omem[oidx] = o;
    *(float4*)&out[(size_t)(b * TT + t) * NOUT + col0] = o;
}

// ---------------- launch ----------------
extern "C" void kernel_launch(void* const* d_in, const int* in_sizes, int n_in,
                              void* d_out, int out_size) {
    const float* x    = (const float*)d_in[0];   // [B, T, NIN]
    const float* wfc1 = (const float*)d_in[1];   // [NIN, NH]
    const float* wrec = (const float*)d_in[2];   // [NH, NH]
    const float* wout = (const float*)d_in[3];   // [NH, NOUT]
    float* out = (float*)d_out;                  // [B, T, NOUT]

    init_state<<<(BB * NH + 255) / 256, 256>>>();
    colsum_rec<<<dim3(NH / 256, NSEG), 256>>>(wrec);
    colsum_out<<<dim3(NOUT / 256, NSEG), 256>>>(wout);
    sgemm_fc1<<<dim3(NH / 128, (BB * TT) / 128), 256>>>(x, wfc1);

    for (int t = 0; t < TT; t++) {
        step_update<<<dim3(BB, NSEG), 128>>>(wrec, t);
        step_out<<<dim3(BB, 2), 128>>>(wout, out, t);
    }
}

// round 5
// speedup vs baseline: 1.5355x; 1.5355x over previous
#include <cuda_runtime.h>
#include <cuda_bf16.h>
#include <cstdint>

// Problem constants
#define BB   128      // batch
#define TT   64       // timesteps
#define NIN  1024
#define NH   4096
#define NOUT 1024
#define NSEG 8
#define SEGSZ 512     // NH / NSEG
#define LCAP 256      // minority list capacity per segment (<= SEGSZ/2)

// ---------------- device scratch (static, no allocations) ----------------
__device__ float d_A[BB * TT * NH];       // fc1 output, row m = b*TT + t  (128 MB)
__device__ float d_hmem[BB * NH];
__device__ float d_spk[BB * NH];
__device__ float d_omem[BB * NOUT];
__device__ int   d_list[2][BB][NSEG][LCAP];
__device__ int   d_cnt[2][BB][NSEG];      // count | (mode << 16); mode=1 => complement list
__device__ float d_csrec[NSEG][NH];       // per-segment column sums of W_rec
__device__ float d_csout[NSEG][NOUT];     // per-segment column sums of W_out

// split-bf16 operands for fc1 tensor-core GEMM
__device__ __nv_bfloat16 d_Ah[BB * TT * NIN];   // 16 MB
__device__ __nv_bfloat16 d_Al[BB * TT * NIN];   // 16 MB
__device__ __nv_bfloat16 d_Bht[NH * NIN];       // W_fc1^T hi  [n][k], 8 MB
__device__ __nv_bfloat16 d_Blt[NH * NIN];       // W_fc1^T lo  [n][k], 8 MB

#define SW128(o) ((o) ^ (((o) >> 3) & 0x70))

// ---------------- base-ISA tensor helpers (compile at compute_103) ----------------
__device__ __forceinline__ void cpasync16(uint32_t dst, const void* src) {
    asm volatile("cp.async.cg.shared.global [%0], [%1], 16;" :: "r"(dst), "l"(src));
}
__device__ __forceinline__ void ldsm_x4(uint32_t& r0, uint32_t& r1, uint32_t& r2, uint32_t& r3,
                                        uint32_t addr) {
    asm volatile("ldmatrix.sync.aligned.m8n8.x4.shared.b16 {%0,%1,%2,%3}, [%4];"
                 : "=r"(r0), "=r"(r1), "=r"(r2), "=r"(r3) : "r"(addr));
}
__device__ __forceinline__ void mma16816(float* c, uint32_t a0, uint32_t a1, uint32_t a2,
                                         uint32_t a3, uint32_t b0, uint32_t b1) {
    asm volatile(
        "mma.sync.aligned.m16n8k16.row.col.f32.bf16.bf16.f32 "
        "{%0,%1,%2,%3}, {%4,%5,%6,%7}, {%8,%9}, {%0,%1,%2,%3};"
        : "+f"(c[0]), "+f"(c[1]), "+f"(c[2]), "+f"(c[3])
        : "r"(a0), "r"(a1), "r"(a2), "r"(a3), "r"(b0), "r"(b1));
}

// ---------------- init ----------------
__global__ void init_state() {
    int i = blockIdx.x * blockDim.x + threadIdx.x;
    if (i < BB * NH)   { d_hmem[i] = 0.0f; d_spk[i] = 0.0f; }
    if (i < BB * NOUT) { d_omem[i] = 0.0f; }
    if (i < 2 * BB * NSEG) { ((int*)d_cnt)[i] = 0; }
}

// ---------------- column sums ----------------
__global__ void colsum_rec(const float* __restrict__ Wrec) {
    int s   = blockIdx.y;
    int col = blockIdx.x * blockDim.x + threadIdx.x;
    float sum = 0.0f;
    const float* base = Wrec + (size_t)(s * SEGSZ) * NH + col;
    #pragma unroll 8
    for (int r = 0; r < SEGSZ; r++) sum += base[(size_t)r * NH];
    d_csrec[s][col] = sum;
}

__global__ void colsum_out(const float* __restrict__ Wout) {
    int s   = blockIdx.y;
    int col = blockIdx.x * blockDim.x + threadIdx.x;
    float sum = 0.0f;
    const float* base = Wout + (size_t)(s * SEGSZ) * NOUT + col;
    #pragma unroll 8
    for (int r = 0; r < SEGSZ; r++) sum += base[(size_t)r * NOUT];
    d_csout[s][col] = sum;
}

// ---------------- split conversions ----------------
__global__ void conv_x(const float* __restrict__ x) {
    int i = (blockIdx.x * blockDim.x + threadIdx.x) * 4;
    float4 v = *(const float4*)(x + i);
    __nv_bfloat16 h0 = __float2bfloat16_rn(v.x);
    __nv_bfloat16 h1 = __float2bfloat16_rn(v.y);
    __nv_bfloat16 h2 = __float2bfloat16_rn(v.z);
    __nv_bfloat16 h3 = __float2bfloat16_rn(v.w);
    __nv_bfloat16 l0 = __float2bfloat16_rn(v.x - __bfloat162float(h0));
    __nv_bfloat16 l1 = __float2bfloat16_rn(v.y - __bfloat162float(h1));
    __nv_bfloat16 l2 = __float2bfloat16_rn(v.z - __bfloat162float(h2));
    __nv_bfloat16 l3 = __float2bfloat16_rn(v.w - __bfloat162float(h3));
    __nv_bfloat162* ph = (__nv_bfloat162*)(d_Ah + i);
    __nv_bfloat162* pl = (__nv_bfloat162*)(d_Al + i);
    ph[0] = __nv_bfloat162(h0, h1); ph[1] = __nv_bfloat162(h2, h3);
    pl[0] = __nv_bfloat162(l0, l1); pl[1] = __nv_bfloat162(l2, l3);
}

// transpose W_fc1 [K=1024][N=4096] -> Bt [N][K], split into hi/lo bf16
__global__ void conv_wt(const float* __restrict__ W) {
    __shared__ float tile[32][33];
    int tx = threadIdx.x, ty = threadIdx.y;         // 32 x 8
    int n0 = blockIdx.x * 32;
    int k0 = blockIdx.y * 32;
    #pragma unroll
    for (int j = 0; j < 32; j += 8)
        tile[ty + j][tx] = W[(size_t)(k0 + ty + j) * NH + n0 + tx];
    __syncthreads();
    #pragma unroll
    for (int j = 0; j < 32; j += 8) {
        float v = tile[tx][ty + j];
        __nv_bfloat16 h = __float2bfloat16_rn(v);
        __nv_bfloat16 l = __float2bfloat16_rn(v - __bfloat162float(h));
        size_t o = (size_t)(n0 + ty + j) * NIN + k0 + tx;
        d_Bht[o] = h;
        d_Blt[o] = l;
    }
}

// ---------------- fc1 via mma.sync: d_A = (Ah+Al) @ (Bh+Bl)^T  (4 terms) ----------------
// CTA tile 128(M) x 128(N), K chunks of 64; tiles Ah/Al/Bh/Bl 16KB each, 2 stages.
#define TILE_B   16384            // one operand tile bytes
#define STAGE_B  (4 * TILE_B)     // 64KB per stage
#define NCHUNK   (NIN / 64)       // 16

__device__ __forceinline__ void load_stage(uint32_t sdst, int c, int by, int bx, int tid) {
    const __nv_bfloat16* srcs[4] = {
        d_Ah  + (size_t)(by * 128) * NIN + c * 64,
        d_Al  + (size_t)(by * 128) * NIN + c * 64,
        d_Bht + (size_t)(bx * 128) * NIN + c * 64,
        d_Blt + (size_t)(bx * 128) * NIN + c * 64
    };
    #pragma unroll
    for (int op = 0; op < 4; op++) {
        uint32_t base = sdst + op * TILE_B;
        const __nv_bfloat16* g = srcs[op];
        #pragma unroll
        for (int i = 0; i < 4; i++) {
            int cid = i * 256 + tid;          // 0..1023
            int row = cid >> 3;
            int kc  = cid & 7;
            uint32_t off = SW128((uint32_t)(row * 128 + kc * 16));
            cpasync16(base + off, g + (size_t)row * NIN + kc * 8);
        }
    }
}

__global__ __launch_bounds__(256, 1) void mma_fc1() {
    extern __shared__ char smem[];
    uint32_t sbase = (uint32_t)__cvta_generic_to_shared(smem);
    int tid  = threadIdx.x;
    int wid  = tid >> 5;
    int lane = tid & 31;
    int wm = wid & 1;          // 2 m-tiles of 64
    int wn = wid >> 1;         // 4 n-tiles of 32
    int bx = blockIdx.x;       // 32 N-tiles
    int by = blockIdx.y;       // 64 M-tiles

    float acc[4][4][4];
    #pragma unroll
    for (int mi = 0; mi < 4; mi++)
        #pragma unroll
        for (int ni = 0; ni < 4; ni++)
            #pragma unroll
            for (int r = 0; r < 4; r++) acc[mi][ni][r] = 0.0f;

    load_stage(sbase, 0, by, bx, tid);
    asm volatile("cp.async.commit_group;");

    int lr  = lane & 7;
    int sub = lane >> 3;
    // precomputed intra-tile offsets for ldmatrix
    uint32_t a_row_base = (uint32_t)(wm * 64 + (sub & 1) * 8 + lr);
    uint32_t a_kb_base  = (uint32_t)((sub >> 1) * 16);
    uint32_t b_row_base = (uint32_t)(wn * 32 + (sub >> 1) * 8 + lr);
    uint32_t b_kb_base  = (uint32_t)((sub & 1) * 16);

    #pragma unroll 1
    for (int c = 0; c < NCHUNK; c++) {
        if (c + 1 < NCHUNK) {
            load_stage(sbase + ((c + 1) & 1) * STAGE_B, c + 1, by, bx, tid);
            asm volatile("cp.async.commit_group;");
            asm volatile("cp.async.wait_group 1;");
        } else {
            asm volatile("cp.async.wait_group 0;");
        }
        __syncthreads();

        uint32_t st = sbase + (c & 1) * STAGE_B;
        uint32_t aHb = st;
        uint32_t aLb = st + TILE_B;
        uint32_t bHb = st + 2 * TILE_B;
        uint32_t bLb = st + 3 * TILE_B;

        #pragma unroll
        for (int ks = 0; ks < 4; ks++) {
            uint32_t aH[4][4], aL[4][4], bH[8], bL[8];
            #pragma unroll
            for (int mi = 0; mi < 4; mi++) {
                uint32_t off = SW128((a_row_base + mi * 16) * 128 + ks * 32 + a_kb_base);
                ldsm_x4(aH[mi][0], aH[mi][1], aH[mi][2], aH[mi][3], aHb + off);
                ldsm_x4(aL[mi][0], aL[mi][1], aL[mi][2], aL[mi][3], aLb + off);
            }
            #pragma unroll
            for (int ng = 0; ng < 2; ng++) {
                uint32_t off = SW128((b_row_base + ng * 16) * 128 + ks * 32 + b_kb_base);
                ldsm_x4(bH[ng * 4 + 0], bH[ng * 4 + 1], bH[ng * 4 + 2], bH[ng * 4 + 3], bHb + off);
                ldsm_x4(bL[ng * 4 + 0], bL[ng * 4 + 1], bL[ng * 4 + 2], bL[ng * 4 + 3], bLb + off);
            }
            #pragma unroll
            for (int mi = 0; mi < 4; mi++)
                #pragma unroll
                for (int ni = 0; ni < 4; ni++) {
                    int bi = (ni >> 1) * 4 + (ni & 1) * 2;
                    mma16816(acc[mi][ni], aH[mi][0], aH[mi][1], aH[mi][2], aH[mi][3],
                             bH[bi], bH[bi + 1]);
                    mma16816(acc[mi][ni], aH[mi][0], aH[mi][1], aH[mi][2], aH[mi][3],
                             bL[bi], bL[bi + 1]);
                    mma16816(acc[mi][ni], aL[mi][0], aL[mi][1], aL[mi][2], aL[mi][3],
                             bH[bi], bH[bi + 1]);
                    mma16816(acc[mi][ni], aL[mi][0], aL[mi][1], aL[mi][2], aL[mi][3],
                             bL[bi], bL[bi + 1]);
                }
        }
        __syncthreads();
    }

    // epilogue: c-frag (row = lane/4 [+8], col = (lane%4)*2 [+1])
    int mrow = by * 128 + wm * 64 + (lane >> 2);
    int ncol = bx * 128 + wn * 32 + (lane & 3) * 2;
    #pragma unroll
    for (int mi = 0; mi < 4; mi++) {
        #pragma unroll
        for (int ni = 0; ni < 4; ni++) {
            float* cf = acc[mi][ni];
            size_t o0 = (size_t)(mrow + mi * 16) * NH + ncol + ni * 8;
            size_t o1 = o0 + (size_t)8 * NH;
            *(float2*)(d_A + o0) = make_float2(cf[0], cf[1]);
            *(float2*)(d_A + o1) = make_float2(cf[2], cf[3]);
        }
    }
}

// ---------------- per-step membrane update + spike + list build ----------------
__global__ __launch_bounds__(128) void step_update(const float* __restrict__ Wrec, int t) {
    int b = blockIdx.x, seg = blockIdx.y, tid = threadIdx.x;
    __shared__ int sh_idx[NSEG * LCAP];
    __shared__ int sh_cnt[NSEG];
    __shared__ int sh_off[NSEG];
    __shared__ int s_total, s_w;

    int rb = (t & 1) ^ 1;
    int wb = t & 1;

    if (tid < NSEG) sh_cnt[tid] = d_cnt[rb][b][tid];
    if (tid == 0) { s_total = 0; s_w = 0; }
    __syncthreads();
    if (tid == 0) {
        int off = 0;
        for (int s = 0; s < NSEG; s++) { sh_off[s] = off; off += (sh_cnt[s] & 0xFFFF); }
    }
    __syncthreads();

    int col0 = seg * SEGSZ + tid * 4;
    float4 r = make_float4(0.f, 0.f, 0.f, 0.f);

    for (int s = 0; s < NSEG; s++) {
        int cm = sh_cnt[s];
        int cnt  = cm & 0xFFFF;
        int mode = cm >> 16;
        if (mode) {
            float4 cs = *(const float4*)&d_csrec[s][col0];
            r.x += cs.x; r.y += cs.y; r.z += cs.z; r.w += cs.w;
        }
        int base = sh_off[s];
        int tag  = (int)((unsigned)mode << 31);
        for (int j = tid; j < cnt; j += blockDim.x)
            sh_idx[base + j] = d_list[rb][b][s][j] | tag;
    }
    __syncthreads();
    int total = sh_off[NSEG - 1] + (sh_cnt[NSEG - 1] & 0xFFFF);

    for (int j = 0; j < total; j++) {
        int v = sh_idx[j];
        float sg = (v >= 0) ? 1.0f : -1.0f;
        const float4 w = *(const float4*)&Wrec[(size_t)(v & 0xFFF) * NH + col0];
        r.x = fmaf(sg, w.x, r.x);
        r.y = fmaf(sg, w.y, r.y);
        r.z = fmaf(sg, w.z, r.z);
        r.w = fmaf(sg, w.w, r.w);
    }

    size_t aidx = (size_t)(b * TT + t) * NH + col0;
    float4 a  = *(const float4*)&d_A[aidx];
    size_t hidx = (size_t)b * NH + col0;
    float4 hm = *(float4*)&d_hmem[hidx];
    float4 sp = *(float4*)&d_spk[hidx];

    hm.x = 0.9f * hm.x * (1.0f - sp.x) + a.x + 0.1f * r.x;
    hm.y = 0.9f * hm.y * (1.0f - sp.y) + a.y + 0.1f * r.y;
    hm.z = 0.9f * hm.z * (1.0f - sp.z) + a.z + 0.1f * r.z;
    hm.w = 0.9f * hm.w * (1.0f - sp.w) + a.w + 0.1f * r.w;

    float4 sn;
    sn.x = hm.x >= 0.5f ? 1.0f : 0.0f;
    sn.y = hm.y >= 0.5f ? 1.0f : 0.0f;
    sn.z = hm.z >= 0.5f ? 1.0f : 0.0f;
    sn.w = hm.w >= 0.5f ? 1.0f : 0.0f;

    *(float4*)&d_hmem[hidx] = hm;
    *(float4*)&d_spk[hidx]  = sn;

    int c = (int)(sn.x + sn.y + sn.z + sn.w);
    atomicAdd(&s_total, c);
    __syncthreads();

    int mode = (s_total > (SEGSZ / 2)) ? 1 : 0;
    float want = mode ? 0.0f : 1.0f;
    int loc[4]; int n = 0;
    if (sn.x == want) loc[n++] = col0 + 0;
    if (sn.y == want) loc[n++] = col0 + 1;
    if (sn.z == want) loc[n++] = col0 + 2;
    if (sn.w == want) loc[n++] = col0 + 3;
    if (n) {
        int p = atomicAdd(&s_w, n);
        for (int k = 0; k < n; k++) d_list[wb][b][seg][p + k] = loc[k];
    }
    __syncthreads();
    if (tid == 0) d_cnt[wb][b][seg] = s_w | (mode << 16);
}

// ---------------- per-step readout ----------------
__global__ __launch_bounds__(128) void step_out(const float* __restrict__ Wout,
                                                float* __restrict__ out, int t) {
    int b = blockIdx.x, half = blockIdx.y, tid = threadIdx.x;
    __shared__ int sh_idx[NSEG * LCAP];
    __shared__ int sh_cnt[NSEG];
    __shared__ int sh_off[NSEG];

    int wb = t & 1;
    if (tid < NSEG) sh_cnt[tid] = d_cnt[wb][b][tid];
    __syncthreads();
    if (tid == 0) {
        int off = 0;
        for (int s = 0; s < NSEG; s++) { sh_off[s] = off; off += (sh_cnt[s] & 0xFFFF); }
    }
    __syncthreads();

    int col0 = half * 512 + tid * 4;
    float4 u = make_float4(0.f, 0.f, 0.f, 0.f);

    for (int s = 0; s < NSEG; s++) {
        int cm = sh_cnt[s];
        int cnt  = cm & 0xFFFF;
        int mode = cm >> 16;
        if (mode) {
            float4 cs = *(const float4*)&d_csout[s][col0];
            u.x += cs.x; u.y += cs.y; u.z += cs.z; u.w += cs.w;
        }
        int base = sh_off[s];
        int tag  = (int)((unsigned)mode << 31);
        for (int j = tid; j < cnt; j += blockDim.x)
            sh_idx[base + j] = d_list[wb][b][s][j] | tag;
    }
    __syncthreads();
    int total = sh_off[NSEG - 1] + (sh_cnt[NSEG - 1] & 0xFFFF);

    for (int j = 0; j < total; j++) {
        int v = sh_idx[j];
        float sg = (v >= 0) ? 1.0f : -1.0f;
        const float4 w = *(const float4*)&Wout[(size_t)(v & 0xFFF) * NOUT + col0];
        u.x = fmaf(sg, w.x, u.x);
        u.y = fmaf(sg, w.y, u.y);
        u.z = fmaf(sg, w.z, u.z);
        u.w = fmaf(sg, w.w, u.w);
    }

    size_t oidx = (size_t)b * NOUT + col0;
    float4 o = *(float4*)&d_omem[oidx];
    o.x = 0.9f * o.x + u.x;
    o.y = 0.9f * o.y + u.y;
    o.z = 0.9f * o.z + u.z;
    o.w = 0.9f * o.w + u.w;
    *(float4*)&d_omem[oidx] = o;
    *(float4*)&out[(size_t)(b * TT + t) * NOUT + col0] = o;
}

// ---------------- launch ----------------
extern "C" void kernel_launch(void* const* d_in, const int* in_sizes, int n_in,
                              void* d_out, int out_size) {
    const float* x    = (const float*)d_in[0];   // [B, T, NIN]
    const float* wfc1 = (const float*)d_in[1];   // [NIN, NH]
    const float* wrec = (const float*)d_in[2];   // [NH, NH]
    const float* wout = (const float*)d_in[3];   // [NH, NOUT]
    float* out = (float*)d_out;                  // [B, T, NOUT]

    static int smem_set = 0;
    if (!smem_set) {
        cudaFuncSetAttribute(mma_fc1, cudaFuncAttributeMaxDynamicSharedMemorySize,
                             2 * STAGE_B);
        smem_set = 1;
    }

    init_state<<<(BB * NH + 255) / 256, 256>>>();
    colsum_rec<<<dim3(NH / 256, NSEG), 256>>>(wrec);
    colsum_out<<<dim3(NOUT / 256, NSEG), 256>>>(wout);
    conv_x<<<(BB * TT * NIN / 4 + 255) / 256, 256>>>(x);
    conv_wt<<<dim3(NH / 32, NIN / 32), dim3(32, 8)>>>(wfc1);
    mma_fc1<<<dim3(NH / 128, (BB * TT) / 128), 256, 2 * STAGE_B>>>();

    for (int t = 0; t < TT; t++) {
        step_update<<<dim3(BB, NSEG), 128>>>(wrec, t);
        step_out<<<dim3(BB, 2), 128>>>(wout, out, t);
    }
}

// round 6
// speedup vs baseline: 2.1838x; 1.4222x over previous
#include <cuda_runtime.h>
#include <cuda_bf16.h>
#include <cstdint>

// Problem constants
#define BB   128      // batch
#define TT   64       // timesteps
#define NIN  1024
#define NH   4096
#define NOUT 1024
#define NSEG 8
#define SEGSZ 512     // NH / NSEG
#define LCAP 256      // minority list capacity per segment (<= SEGSZ/2)

// ---------------- device scratch (static, no allocations) ----------------
__device__ float d_A[BB * TT * NH];       // fc1 output, row m = b*TT + t  (128 MB)
__device__ float d_csrec[NSEG][NH];       // per-segment column sums of W_rec
__device__ float d_csout[NSEG][NOUT];     // per-segment column sums of W_out

// split-bf16 operands for fc1 tensor-core GEMM
__device__ __nv_bfloat16 d_Ah[BB * TT * NIN];   // 16 MB
__device__ __nv_bfloat16 d_Al[BB * TT * NIN];   // 16 MB
__device__ __nv_bfloat16 d_Bht[NH * NIN];       // W_fc1^T hi  [n][k], 8 MB
__device__ __nv_bfloat16 d_Blt[NH * NIN];       // W_fc1^T lo  [n][k], 8 MB

#define SW128(o) ((o) ^ (((o) >> 3) & 0x70))

// ---------------- base-ISA tensor helpers (compile at compute_103) ----------------
__device__ __forceinline__ void cpasync16(uint32_t dst, const void* src) {
    asm volatile("cp.async.cg.shared.global [%0], [%1], 16;" :: "r"(dst), "l"(src));
}
__device__ __forceinline__ void ldsm_x4(uint32_t& r0, uint32_t& r1, uint32_t& r2, uint32_t& r3,
                                        uint32_t addr) {
    asm volatile("ldmatrix.sync.aligned.m8n8.x4.shared.b16 {%0,%1,%2,%3}, [%4];"
                 : "=r"(r0), "=r"(r1), "=r"(r2), "=r"(r3) : "r"(addr));
}
__device__ __forceinline__ void mma16816(float* c, uint32_t a0, uint32_t a1, uint32_t a2,
                                         uint32_t a3, uint32_t b0, uint32_t b1) {
    asm volatile(
        "mma.sync.aligned.m16n8k16.row.col.f32.bf16.bf16.f32 "
        "{%0,%1,%2,%3}, {%4,%5,%6,%7}, {%8,%9}, {%0,%1,%2,%3};"
        : "+f"(c[0]), "+f"(c[1]), "+f"(c[2]), "+f"(c[3])
        : "r"(a0), "r"(a1), "r"(a2), "r"(a3), "r"(b0), "r"(b1));
}

// ---------------- column sums ----------------
__global__ void colsum_rec(const float* __restrict__ Wrec) {
    int s   = blockIdx.y;
    int col = blockIdx.x * blockDim.x + threadIdx.x;
    float sum = 0.0f;
    const float* base = Wrec + (size_t)(s * SEGSZ) * NH + col;
    #pragma unroll 8
    for (int r = 0; r < SEGSZ; r++) sum += base[(size_t)r * NH];
    d_csrec[s][col] = sum;
}

__global__ void colsum_out(const float* __restrict__ Wout) {
    int s   = blockIdx.y;
    int col = blockIdx.x * blockDim.x + threadIdx.x;
    float sum = 0.0f;
    const float* base = Wout + (size_t)(s * SEGSZ) * NOUT + col;
    #pragma unroll 8
    for (int r = 0; r < SEGSZ; r++) sum += base[(size_t)r * NOUT];
    d_csout[s][col] = sum;
}

// ---------------- split conversions ----------------
__global__ void conv_x(const float* __restrict__ x) {
    int i = (blockIdx.x * blockDim.x + threadIdx.x) * 4;
    float4 v = *(const float4*)(x + i);
    __nv_bfloat16 h0 = __float2bfloat16_rn(v.x);
    __nv_bfloat16 h1 = __float2bfloat16_rn(v.y);
    __nv_bfloat16 h2 = __float2bfloat16_rn(v.z);
    __nv_bfloat16 h3 = __float2bfloat16_rn(v.w);
    __nv_bfloat16 l0 = __float2bfloat16_rn(v.x - __bfloat162float(h0));
    __nv_bfloat16 l1 = __float2bfloat16_rn(v.y - __bfloat162float(h1));
    __nv_bfloat16 l2 = __float2bfloat16_rn(v.z - __bfloat162float(h2));
    __nv_bfloat16 l3 = __float2bfloat16_rn(v.w - __bfloat162float(h3));
    __nv_bfloat162* ph = (__nv_bfloat162*)(d_Ah + i);
    __nv_bfloat162* pl = (__nv_bfloat162*)(d_Al + i);
    ph[0] = __nv_bfloat162(h0, h1); ph[1] = __nv_bfloat162(h2, h3);
    pl[0] = __nv_bfloat162(l0, l1); pl[1] = __nv_bfloat162(l2, l3);
}

// transpose W_fc1 [K=1024][N=4096] -> Bt [N][K], split into hi/lo bf16
__global__ void conv_wt(const float* __restrict__ W) {
    __shared__ float tile[32][33];
    int tx = threadIdx.x, ty = threadIdx.y;         // 32 x 8
    int n0 = blockIdx.x * 32;
    int k0 = blockIdx.y * 32;
    #pragma unroll
    for (int j = 0; j < 32; j += 8)
        tile[ty + j][tx] = W[(size_t)(k0 + ty + j) * NH + n0 + tx];
    __syncthreads();
    #pragma unroll
    for (int j = 0; j < 32; j += 8) {
        float v = tile[tx][ty + j];
        __nv_bfloat16 h = __float2bfloat16_rn(v);
        __nv_bfloat16 l = __float2bfloat16_rn(v - __bfloat162float(h));
        size_t o = (size_t)(n0 + ty + j) * NIN + k0 + tx;
        d_Bht[o] = h;
        d_Blt[o] = l;
    }
}

// ---------------- fc1 via mma.sync: d_A = Ah@Bh + Ah@Bl + Al@Bh  (3 terms) ----------------
#define TILE_B   16384            // one operand tile bytes
#define STAGE_B  (4 * TILE_B)     // 64KB per stage
#define NCHUNK   (NIN / 64)       // 16

__device__ __forceinline__ void load_stage(uint32_t sdst, int c, int by, int bx, int tid) {
    const __nv_bfloat16* srcs[4] = {
        d_Ah  + (size_t)(by * 128) * NIN + c * 64,
        d_Al  + (size_t)(by * 128) * NIN + c * 64,
        d_Bht + (size_t)(bx * 128) * NIN + c * 64,
        d_Blt + (size_t)(bx * 128) * NIN + c * 64
    };
    #pragma unroll
    for (int op = 0; op < 4; op++) {
        uint32_t base = sdst + op * TILE_B;
        const __nv_bfloat16* g = srcs[op];
        #pragma unroll
        for (int i = 0; i < 4; i++) {
            int cid = i * 256 + tid;          // 0..1023
            int row = cid >> 3;
            int kc  = cid & 7;
            uint32_t off = SW128((uint32_t)(row * 128 + kc * 16));
            cpasync16(base + off, g + (size_t)row * NIN + kc * 8);
        }
    }
}

__global__ __launch_bounds__(256, 1) void mma_fc1() {
    extern __shared__ char smem[];
    uint32_t sbase = (uint32_t)__cvta_generic_to_shared(smem);
    int tid  = threadIdx.x;
    int wid  = tid >> 5;
    int lane = tid & 31;
    int wm = wid & 1;          // 2 m-tiles of 64
    int wn = wid >> 1;         // 4 n-tiles of 32
    int bx = blockIdx.x;       // 32 N-tiles
    int by = blockIdx.y;       // 64 M-tiles

    float acc[4][4][4];
    #pragma unroll
    for (int mi = 0; mi < 4; mi++)
        #pragma unroll
        for (int ni = 0; ni < 4; ni++)
            #pragma unroll
            for (int r = 0; r < 4; r++) acc[mi][ni][r] = 0.0f;

    load_stage(sbase, 0, by, bx, tid);
    asm volatile("cp.async.commit_group;");

    int lr  = lane & 7;
    int sub = lane >> 3;
    uint32_t a_row_base = (uint32_t)(wm * 64 + (sub & 1) * 8 + lr);
    uint32_t a_kb_base  = (uint32_t)((sub >> 1) * 16);
    uint32_t b_row_base = (uint32_t)(wn * 32 + (sub >> 1) * 8 + lr);
    uint32_t b_kb_base  = (uint32_t)((sub & 1) * 16);

    #pragma unroll 1
    for (int c = 0; c < NCHUNK; c++) {
        if (c + 1 < NCHUNK) {
            load_stage(sbase + ((c + 1) & 1) * STAGE_B, c + 1, by, bx, tid);
            asm volatile("cp.async.commit_group;");
            asm volatile("cp.async.wait_group 1;");
        } else {
            asm volatile("cp.async.wait_group 0;");
        }
        __syncthreads();

        uint32_t st = sbase + (c & 1) * STAGE_B;
        uint32_t aHb = st;
        uint32_t aLb = st + TILE_B;
        uint32_t bHb = st + 2 * TILE_B;
        uint32_t bLb = st + 3 * TILE_B;

        #pragma unroll
        for (int ks = 0; ks < 4; ks++) {
            uint32_t aH[4][4], aL[4][4], bH[8], bL[8];
            #pragma unroll
            for (int mi = 0; mi < 4; mi++) {
                uint32_t off = SW128((a_row_base + mi * 16) * 128 + ks * 32 + a_kb_base);
                ldsm_x4(aH[mi][0], aH[mi][1], aH[mi][2], aH[mi][3], aHb + off);
                ldsm_x4(aL[mi][0], aL[mi][1], aL[mi][2], aL[mi][3], aLb + off);
            }
            #pragma unroll
            for (int ng = 0; ng < 2; ng++) {
                uint32_t off = SW128((b_row_base + ng * 16) * 128 + ks * 32 + b_kb_base);
                ldsm_x4(bH[ng * 4 + 0], bH[ng * 4 + 1], bH[ng * 4 + 2], bH[ng * 4 + 3], bHb + off);
                ldsm_x4(bL[ng * 4 + 0], bL[ng * 4 + 1], bL[ng * 4 + 2], bL[ng * 4 + 3], bLb + off);
            }
            #pragma unroll
            for (int mi = 0; mi < 4; mi++)
                #pragma unroll
                for (int ni = 0; ni < 4; ni++) {
                    int bi = (ni >> 1) * 4 + (ni & 1) * 2;
                    mma16816(acc[mi][ni], aH[mi][0], aH[mi][1], aH[mi][2], aH[mi][3],
                             bH[bi], bH[bi + 1]);
                    mma16816(acc[mi][ni], aH[mi][0], aH[mi][1], aH[mi][2], aH[mi][3],
                             bL[bi], bL[bi + 1]);
                    mma16816(acc[mi][ni], aL[mi][0], aL[mi][1], aL[mi][2], aL[mi][3],
                             bH[bi], bH[bi + 1]);
                }
        }
        __syncthreads();
    }

    int mrow = by * 128 + wm * 64 + (lane >> 2);
    int ncol = bx * 128 + wn * 32 + (lane & 3) * 2;
    #pragma unroll
    for (int mi = 0; mi < 4; mi++) {
        #pragma unroll
        for (int ni = 0; ni < 4; ni++) {
            float* cf = acc[mi][ni];
            size_t o0 = (size_t)(mrow + mi * 16) * NH + ncol + ni * 8;
            size_t o1 = o0 + (size_t)8 * NH;
            *(float2*)(d_A + o0) = make_float2(cf[0], cf[1]);
            *(float2*)(d_A + o1) = make_float2(cf[2], cf[3]);
        }
    }
}

// ---------------- fused persistent scan: one CTA per batch element ----------------
// 512 threads; thread owns hidden cols [8*tid, 8*tid+8) and output cols [2*tid, 2*tid+2).
// hm/spk/o_mem live in registers for all 64 steps; minority lists double-buffered in shared.
__global__ __launch_bounds__(512, 1) void fused_steps(const float* __restrict__ Wrec,
                                                      const float* __restrict__ Wout,
                                                      float* __restrict__ out) {
    int b = blockIdx.x, tid = threadIdx.x;
    int seg  = tid >> 6;          // 64 threads per segment (64*8 = 512 cols)
    int col0 = tid * 8;
    int oc   = tid * 2;

    __shared__ int sh_list[2][NSEG][LCAP];
    __shared__ int sh_cnt[2][NSEG];    // cnt | (mode << 16)
    __shared__ int sh_spk[NSEG];
    __shared__ int sh_pos[NSEG];

    float hm[8], sp[8];
    #pragma unroll
    for (int i = 0; i < 8; i++) { hm[i] = 0.0f; sp[i] = 0.0f; }
    float ox = 0.0f, oy = 0.0f;

    if (tid < NSEG) { sh_cnt[0][tid] = 0; sh_cnt[1][tid] = 0; }
    __syncthreads();

    for (int t = 0; t < TT; t++) {
        int rbuf = (t & 1) ^ 1, wbuf = t & 1;

        // --- 1. recurrent drive from prev-step minority lists ---
        float r[8];
        #pragma unroll
        for (int i = 0; i < 8; i++) r[i] = 0.0f;

        for (int s = 0; s < NSEG; s++) {
            int cm = sh_cnt[rbuf][s];
            int cnt = cm & 0xFFFF;
            int mode = cm >> 16;
            float sg = mode ? -1.0f : 1.0f;
            if (mode) {
                float4 c0 = *(const float4*)&d_csrec[s][col0];
                float4 c1 = *(const float4*)&d_csrec[s][col0 + 4];
                r[0] += c0.x; r[1] += c0.y; r[2] += c0.z; r[3] += c0.w;
                r[4] += c1.x; r[5] += c1.y; r[6] += c1.z; r[7] += c1.w;
            }
            #pragma unroll 2
            for (int j = 0; j < cnt; j++) {
                int idx = sh_list[rbuf][s][j];
                const float* wr = Wrec + (size_t)idx * NH + col0;
                float4 w0 = *(const float4*)wr;
                float4 w1 = *(const float4*)(wr + 4);
                r[0] = fmaf(sg, w0.x, r[0]); r[1] = fmaf(sg, w0.y, r[1]);
                r[2] = fmaf(sg, w0.z, r[2]); r[3] = fmaf(sg, w0.w, r[3]);
                r[4] = fmaf(sg, w1.x, r[4]); r[5] = fmaf(sg, w1.y, r[5]);
                r[6] = fmaf(sg, w1.z, r[6]); r[7] = fmaf(sg, w1.w, r[7]);
            }
        }

        // --- 2. membrane update + spikes ---
        const float* ap = d_A + (size_t)(b * TT + t) * NH + col0;
        float4 a0 = *(const float4*)ap;
        float4 a1 = *(const float4*)(ap + 4);
        float a[8] = {a0.x, a0.y, a0.z, a0.w, a1.x, a1.y, a1.z, a1.w};
        int nsp = 0;
        #pragma unroll
        for (int i = 0; i < 8; i++) {
            hm[i] = 0.9f * hm[i] * (1.0f - sp[i]) + a[i] + 0.1f * r[i];
            sp[i] = (hm[i] >= 0.5f) ? 1.0f : 0.0f;
            nsp += (int)sp[i];
        }

        // --- 3. per-seg spike count -> minority mode -> build lists ---
        if (tid < NSEG) { sh_spk[tid] = 0; sh_pos[tid] = 0; }
        __syncthreads();                                   // B1
        if (nsp) atomicAdd(&sh_spk[seg], nsp);
        __syncthreads();                                   // B2
        int mode = (sh_spk[seg] > (SEGSZ / 2)) ? 1 : 0;
        float want = mode ? 0.0f : 1.0f;
        int loc[8], n = 0;
        #pragma unroll
        for (int i = 0; i < 8; i++)
            if (sp[i] == want) loc[n++] = col0 + i;
        if (n) {
            int p = atomicAdd(&sh_pos[seg], n);
            for (int k = 0; k < n; k++) sh_list[wbuf][seg][p + k] = loc[k];
        }
        __syncthreads();                                   // B3
        if (tid < NSEG)
            sh_cnt[wbuf][tid] = sh_pos[tid] | (((sh_spk[tid] > (SEGSZ / 2)) ? 1 : 0) << 16);
        __syncthreads();                                   // B4

        // --- 4. readout via this step's lists ---
        float ux = 0.0f, uy = 0.0f;
        for (int s = 0; s < NSEG; s++) {
            int cm = sh_cnt[wbuf][s];
            int cnt = cm & 0xFFFF;
            int mode2 = cm >> 16;
            float sg = mode2 ? -1.0f : 1.0f;
            if (mode2) {
                float2 cs = *(const float2*)&d_csout[s][oc];
                ux += cs.x; uy += cs.y;
            }
            #pragma unroll 4
            for (int j = 0; j < cnt; j++) {
                int idx = sh_list[wbuf][s][j];
                float2 w = *(const float2*)(Wout + (size_t)idx * NOUT + oc);
                ux = fmaf(sg, w.x, ux);
                uy = fmaf(sg, w.y, uy);
            }
        }
        ox = 0.9f * ox + ux;
        oy = 0.9f * oy + uy;
        *(float2*)(out + (size_t)(b * TT + t) * NOUT + oc) = make_float2(ox, oy);
    }
}

// ---------------- launch ----------------
extern "C" void kernel_launch(void* const* d_in, const int* in_sizes, int n_in,
                              void* d_out, int out_size) {
    const float* x    = (const float*)d_in[0];   // [B, T, NIN]
    const float* wfc1 = (const float*)d_in[1];   // [NIN, NH]
    const float* wrec = (const float*)d_in[2];   // [NH, NH]
    const float* wout = (const float*)d_in[3];   // [NH, NOUT]
    float* out = (float*)d_out;                  // [B, T, NOUT]

    static int smem_set = 0;
    if (!smem_set) {
        cudaFuncSetAttribute(mma_fc1, cudaFuncAttributeMaxDynamicSharedMemorySize,
                             2 * STAGE_B);
        smem_set = 1;
    }

    colsum_rec<<<dim3(NH / 256, NSEG), 256>>>(wrec);
    colsum_out<<<dim3(NOUT / 256, NSEG), 256>>>(wout);
    conv_x<<<(BB * TT * NIN / 4 + 255) / 256, 256>>>(x);
    conv_wt<<<dim3(NH / 32, NIN / 32), dim3(32, 8)>>>(wfc1);
    mma_fc1<<<dim3(NH / 128, (BB * TT) / 128), 256, 2 * STAGE_B>>>();
    fused_steps<<<BB, 512>>>(wrec, wout, out);
}